// round 4
// baseline (speedup 1.0000x reference)
#include <cuda_runtime.h>

#define NT 128
#define CPT 3   // cells per thread

// physics constants (gamma = 5/3)
#define GAMMA_F   1.6666666666666667f
#define SG_F      0.8164965809277260f   // sqrt(gamma-1)
#define GM1_F     0.6666666666666667f   // gamma-1
#define LN2_SG    0.8489271574f         // ln2 / SG
#define HLN2      0.3465735903f         // 0.5*ln2

typedef unsigned long long u64;

__device__ __forceinline__ float fdivf_(float a, float b){ return __fdividef(a, b); }

__device__ __forceinline__ u64 pk2(float lo, float hi){
    u64 r; asm("mov.b64 %0, {%1, %2};" : "=l"(r) : "f"(lo), "f"(hi)); return r;
}
__device__ __forceinline__ void upk2(u64 v, float& lo, float& hi){
    asm("mov.b64 {%0, %1}, %2;" : "=f"(lo), "=f"(hi) : "l"(v));
}
__device__ __forceinline__ u64 fma2(u64 a, u64 b, u64 c){
    u64 d; asm("fma.rn.f32x2 %0, %1, %2, %3;" : "=l"(d) : "l"(a), "l"(b), "l"(c)); return d;
}
__device__ __forceinline__ u64 add2(u64 a, u64 b){
    u64 d; asm("add.rn.f32x2 %0, %1, %2;" : "=l"(d) : "l"(a), "l"(b)); return d;
}

// hardware MUFU.TANH — validated few-ulp accurate on this data (R2->R3 rel_err delta 7e-8)
__device__ __forceinline__ float tanh_ap(float x){
    float y; asm("tanh.approx.f32 %0, %1;" : "=f"(y) : "f"(x)); return y;
}
__device__ __forceinline__ float sqrt_ap(float x){
    float y; asm("sqrt.approx.f32 %0, %1;" : "=f"(y) : "f"(x)); return y;
}

__device__ __forceinline__ float csnd(float rho, float p){
    return sqrt_ap(fdivf_(GAMMA_F * p, rho + 2.5f * p));
}

// vstar in log space: tanh(atanh_v + coeff*(lg2(SG-cs)-lg2(SG+cs)+lgK))
__device__ __forceinline__ float vstar_log(float cs, float atanh_v, float lgK, float coeff){
    float t = __log2f(SG_F - cs) - __log2f(SG_F + cs) + lgK;
    return tanh_ap(fmaf(coeff, t, atanh_v));
}

// bisection rarefaction solver; sgn = +1 (left) / -1 (right)
__device__ __forceinline__ void raref_solve(
    float rho_a, float p_a, float sgn, float atanh_v, float lgK,
    float& rho_o, float& p_o, float& h_o, float& v_o)
{
    float coeff = sgn * LN2_SG;
    float lo = 1e-6f;
    float hi = SG_F - 1e-6f;
    float flo = vstar_log(lo, atanh_v, lgK, coeff) - sgn * lo;
    #pragma unroll 1
    for (int i = 0; i < 20; i++){
        float mid = 0.5f * (lo + hi);
        float fm = vstar_log(mid, atanh_v, lgK, coeff) - sgn * mid;
        bool same = ((fm > 0.0f) == (flo > 0.0f)) && ((fm < 0.0f) == (flo < 0.0f));
        if (same){ lo = mid; flo = fm; } else { hi = mid; }
    }
    float cs = 0.5f * (lo + hi);
    float h  = fdivf_(GM1_F, GM1_F - cs * cs);
    float k  = (h - 1.0f) * 0.4f;
    float base = fdivf_(k * __powf(rho_a, GAMMA_F), p_a);
    rho_o = base * sqrt_ap(base);
    p_o   = k * rho_o;
    h_o   = h;
    v_o   = sgn * cs;
}

// shared-memory layout (floats)
#define OFF_W1T 0        // [5][6][32]  = 960 (transposed: e,f,h)
#define OFF_W2  960      // [5][32][32] = 5120 (e,g,h)
#define OFF_B1  6080     // [5][32]
#define OFF_B2  6240     // [5][32]
#define OFF_W3  6400     // [5][32]
#define OFF_B3  6560     // [5] (+pad)
#define SM_TOT  6568

// per-cell physics phase: argmin over ensemble + wave speeds + flux selection
__device__ __forceinline__ void physics_phase(
    int n, int NC, const float* __restrict__ P, const float* __restrict__ F,
    const float* __restrict__ pc, float* __restrict__ out)
{
    int cc = n < NC ? n : NC - 1;
    const float* Pb = P + (size_t)cc * 6;
    float rhoL = Pb[0], rhoR = Pb[1];
    float pL   = Pb[2], pR   = Pb[3];
    float vL   = Pb[4], vR   = Pb[5];

    float csL = csnd(rhoL, pL);
    float csR = csnd(rhoR, pR);
    float atanhL = HLN2 * (__log2f(1.0f + vL) - __log2f(1.0f - vL));
    float atanhR = HLN2 * (__log2f(1.0f + vR) - __log2f(1.0f - vR));
    float lgKL = __log2f(SG_F + csL) - __log2f(SG_F - csL);
    float lgKR = __log2f(SG_F + csR) - __log2f(SG_F - csR);
    float invpL = fdivf_(1.0f, pL);
    float invpR = fdivf_(1.0f, pR);

    float bestd = 1e30f;
    float s_press = 0.f, s_rhoCL = 0.f, s_hCL = 0.f, s_csCL = 0.f, s_vstarL = 0.f;
    float s_rhoCR = 0.f, s_hCR = 0.f, s_csCR = 0.f, s_vstarR = 0.f;

    #pragma unroll
    for (int e = 0; e < 5; e++){
        float p_c = pc[e];
        float rhoCL = rhoL * __powf(p_c * invpL, 0.6f);
        float hCL   = 1.0f + 2.5f * fdivf_(p_c, rhoCL);
        float csCL  = sqrt_ap(fdivf_(GAMMA_F * p_c, rhoCL + 2.5f * p_c));
        float vsL   = vstar_log(csCL, atanhL, lgKL, +LN2_SG);

        float rhoCR = rhoR * __powf(p_c * invpR, 0.6f);
        float hCR   = 1.0f + 2.5f * fdivf_(p_c, rhoCR);
        float csCR  = sqrt_ap(fdivf_(GAMMA_F * p_c, rhoCR + 2.5f * p_c));
        float vsR   = vstar_log(csCR, atanhR, lgKR, -LN2_SG);

        float d = fabsf(vsL - vsR);
        if (d < bestd){
            bestd = d; s_press = p_c;
            s_rhoCL = rhoCL; s_hCL = hCL; s_csCL = csCL; s_vstarL = vsL;
            s_rhoCR = rhoCR; s_hCR = hCR; s_csCR = csCR; s_vstarR = vsR;
        }
    }

    float lamC  = 0.5f * (s_vstarR + s_vstarL);
    float lamRL = fdivf_(lamC - s_csCL, 1.0f - lamC * s_csCL);
    float lamL  = fdivf_(vL - csL,     1.0f - vL * csL);
    float lamRR = fdivf_(lamC + s_csCR, 1.0f + lamC * s_csCR);
    float lamR  = fdivf_(vR + csR,     1.0f + vR * csR);

    int win = 0;
    if (lamL >= 0.0f)                   win = 1;
    if (lamL < 0.0f && lamRL >= 0.0f)   win = 2;
    if (lamRL < 0.0f && lamC > 0.0f)    win = 3;
    if (lamC <= 0.0f && lamRR > 0.0f)   win = 4;
    if (lamRR <= 0.0f && lamR > 0.0f)   win = 5;
    if (lamR <= 0.0f)                   win = 6;

    float f0 = 0.f, f1 = 0.f, f2 = 0.f;

    const float* Fb = F + (size_t)cc * 6;
    if (win == 1){ f0 = Fb[0]; f1 = Fb[2]; f2 = Fb[4]; }
    if (win == 6){ f0 = Fb[1]; f1 = Fb[3]; f2 = Fb[5]; }

    if (win == 3 || win == 4){
        float WC = rsqrtf(1.0f - lamC * lamC);
        float rc = (win == 3) ? s_rhoCL : s_rhoCR;
        float hc = (win == 3) ? s_hCL   : s_hCR;
        float dens = WC * rc;
        float mom  = WC * WC * rc * hc * lamC;
        f0 = dens * lamC;
        f1 = dens * (WC * hc - 1.0f) * lamC;
        f2 = mom * lamC + s_press;
    }

    bool needL = (win == 2);
    unsigned m = __activemask();
    if (__any_sync(m, needL)){
        float r_, p_, h_, v_;
        raref_solve(rhoL, pL, +1.0f, atanhL, lgKL, r_, p_, h_, v_);
        if (needL){
            float W_ = rsqrtf(1.0f - v_ * v_);
            float dens = W_ * r_;
            float mom  = W_ * W_ * r_ * h_ * v_;
            f0 = dens * v_;
            f1 = dens * (W_ * h_ - 1.0f) * v_;
            f2 = mom * v_ + p_;
        }
    }
    bool needR = (win == 5);
    if (__any_sync(m, needR)){
        float r_, p_, h_, v_;
        raref_solve(rhoR, pR, -1.0f, atanhR, lgKR, r_, p_, h_, v_);
        if (needR){
            float W_ = rsqrtf(1.0f - v_ * v_);
            float dens = W_ * r_;
            float mom  = W_ * W_ * r_ * h_ * v_;
            f0 = dens * v_;
            f1 = dens * (W_ * h_ - 1.0f) * v_;
            f2 = mom * v_ + p_;
        }
    }

    if (n < NC){
        float* ob = out + (size_t)n * 3;
        ob[0] = f0; ob[1] = f1; ob[2] = f2;
    }
}

__global__ void __launch_bounds__(NT)
ensemble_raref_kernel(
    const float* __restrict__ P,  const float* __restrict__ F,
    const float* __restrict__ W1, const float* __restrict__ b1,
    const float* __restrict__ W2, const float* __restrict__ b2,
    const float* __restrict__ W3, const float* __restrict__ b3,
    float* __restrict__ out, int NC)
{
    __shared__ __align__(16) float sm[SM_TOT];
    const int tid = threadIdx.x;

    for (int i = tid; i < 960; i += NT){
        int e = i / 192, r = i % 192, h = r / 6, f = r % 6;
        sm[OFF_W1T + e * 192 + f * 32 + h] = W1[i];
    }
    for (int i = tid; i < 5120; i += NT) sm[OFF_W2 + i] = W2[i];
    for (int i = tid; i < 160; i += NT){
        sm[OFF_B1 + i] = b1[i];
        sm[OFF_B2 + i] = b2[i];
        sm[OFF_W3 + i] = W3[i];
    }
    if (tid < 5) sm[OFF_B3 + tid] = b3[tid];
    __syncthreads();

    const int base = blockIdx.x * (CPT * NT);
    int ncell[CPT];
    float xv[CPT][6];
    float pmin[CPT];
    float pcv[CPT][5];

    #pragma unroll
    for (int c = 0; c < CPT; c++){
        int n = base + c * NT + tid;
        ncell[c] = n;
        int cc = n < NC ? n : NC - 1;
        const float* Pb = P + (size_t)cc * 6;
        float r0 = Pb[0], r1 = Pb[1], p0 = Pb[2], p1 = Pb[3], v0 = Pb[4], v1 = Pb[5];
        xv[c][0] = __logf(r0); xv[c][1] = __logf(r1);
        xv[c][2] = __logf(p0); xv[c][3] = __logf(p1);
        xv[c][4] = v0;         xv[c][5] = v1;
        pmin[c] = fminf(p0, p1);
    }

    // ---- Phase A: MLP for CPT cells (weight LDS amortized) ----
    #pragma unroll 1
    for (int e = 0; e < 5; e++){
        const float* w1 = &sm[OFF_W1T + e * 192];

        u64 hh[CPT][16];
        {
            const ulonglong2* bp = (const ulonglong2*)&sm[OFF_B1 + e * 32];
            #pragma unroll
            for (int q = 0; q < 8; q++){
                ulonglong2 b = bp[q];
                #pragma unroll
                for (int c = 0; c < CPT; c++){ hh[c][2*q] = b.x; hh[c][2*q+1] = b.y; }
            }
        }
        #pragma unroll
        for (int f = 0; f < 6; f++){
            u64 xp[CPT];
            #pragma unroll
            for (int c = 0; c < CPT; c++) xp[c] = pk2(xv[c][f], xv[c][f]);
            const ulonglong2* wrow = (const ulonglong2*)(w1 + f * 32);
            #pragma unroll
            for (int q = 0; q < 8; q++){
                ulonglong2 w = wrow[q];
                #pragma unroll
                for (int c = 0; c < CPT; c++){
                    hh[c][2*q]   = fma2(xp[c], w.x, hh[c][2*q]);
                    hh[c][2*q+1] = fma2(xp[c], w.y, hh[c][2*q+1]);
                }
            }
        }
        #pragma unroll
        for (int q = 0; q < 16; q++){
            #pragma unroll
            for (int c = 0; c < CPT; c++){
                float u, v; upk2(hh[c][q], u, v);
                hh[c][q] = pk2(tanh_ap(u), tanh_ap(v));
            }
        }

        const float* w2  = &sm[OFF_W2 + e * 1024];
        const float* bb2 = &sm[OFF_B2 + e * 32];
        const float* w3  = &sm[OFF_W3 + e * 32];
        float logit[CPT];
        float b3v = sm[OFF_B3 + e];
        #pragma unroll
        for (int c = 0; c < CPT; c++) logit[c] = b3v;

        #pragma unroll 4
        for (int g = 0; g < 32; g++){
            float bg = bb2[g];
            u64 a0[CPT], a1[CPT];
            #pragma unroll
            for (int c = 0; c < CPT; c++){ a0[c] = pk2(bg, 0.0f); a1[c] = pk2(0.0f, 0.0f); }
            const ulonglong2* wrow = (const ulonglong2*)(w2 + g * 32);
            #pragma unroll
            for (int q = 0; q < 8; q++){
                ulonglong2 w = wrow[q];
                #pragma unroll
                for (int c = 0; c < CPT; c++){
                    a0[c] = fma2(hh[c][2*q],   w.x, a0[c]);
                    a1[c] = fma2(hh[c][2*q+1], w.y, a1[c]);
                }
            }
            float wg = w3[g];
            #pragma unroll
            for (int c = 0; c < CPT; c++){
                u64 s = add2(a0[c], a1[c]);
                float s0, s1; upk2(s, s0, s1);
                logit[c] = fmaf(wg, tanh_ap(s0 + s1), logit[c]);
            }
        }
        #pragma unroll
        for (int c = 0; c < CPT; c++)
            pcv[c][e] = fmaf(0.5f, tanh_ap(0.5f * logit[c]), 0.5f) * pmin[c];
    }

    // ---- Phase B: physics per cell ----
    #pragma unroll 1
    for (int c = 0; c < CPT; c++)
        physics_phase(ncell[c], NC, P, F, pcv[c], out);
}

extern "C" void kernel_launch(void* const* d_in, const int* in_sizes, int n_in,
                              void* d_out, int out_size)
{
    const float* P  = (const float*)d_in[0];
    const float* F  = (const float*)d_in[2];
    const float* W1 = (const float*)d_in[5];
    const float* b1 = (const float*)d_in[6];
    const float* W2 = (const float*)d_in[7];
    const float* b2 = (const float*)d_in[8];
    const float* W3 = (const float*)d_in[9];
    const float* b3 = (const float*)d_in[10];
    float* out = (float*)d_out;

    int NC = in_sizes[0] / 6;
    int cellsPerBlock = CPT * NT;
    int grid = (NC + cellsPerBlock - 1) / cellsPerBlock;
    ensemble_raref_kernel<<<grid, NT>>>(P, F, W1, b1, W2, b2, W3, b3, out, NC);
}

// round 5
// speedup vs baseline: 1.3126x; 1.3126x over previous
#include <cuda_runtime.h>

#define NT 128

// physics constants (gamma = 5/3)
#define GAMMA_F   1.6666666666666667f
#define SG_F      0.8164965809277260f   // sqrt(gamma-1)
#define GM1_F     0.6666666666666667f   // gamma-1
#define LN2_SG    0.8489271574f         // ln2 / SG
#define HLN2      0.3465735903f         // 0.5*ln2

typedef unsigned long long u64;

__device__ __forceinline__ float fdivf_(float a, float b){ return __fdividef(a, b); }

__device__ __forceinline__ u64 pk2(float lo, float hi){
    u64 r; asm("mov.b64 %0, {%1, %2};" : "=l"(r) : "f"(lo), "f"(hi)); return r;
}
__device__ __forceinline__ void upk2(u64 v, float& lo, float& hi){
    asm("mov.b64 {%0, %1}, %2;" : "=f"(lo), "=f"(hi) : "l"(v));
}
__device__ __forceinline__ u64 fma2(u64 a, u64 b, u64 c){
    u64 d; asm("fma.rn.f32x2 %0, %1, %2, %3;" : "=l"(d) : "l"(a), "l"(b), "l"(c)); return d;
}
__device__ __forceinline__ u64 add2(u64 a, u64 b){
    u64 d; asm("add.rn.f32x2 %0, %1, %2;" : "=l"(d) : "l"(a), "l"(b)); return d;
}

// hardware MUFU.TANH / MUFU.SQRT — validated: rel_err 3.1e-6 end-to-end (R4)
__device__ __forceinline__ float tanh_ap(float x){
    float y; asm("tanh.approx.f32 %0, %1;" : "=f"(y) : "f"(x)); return y;
}
__device__ __forceinline__ float sqrt_ap(float x){
    float y; asm("sqrt.approx.f32 %0, %1;" : "=f"(y) : "f"(x)); return y;
}

__device__ __forceinline__ float csnd(float rho, float p){
    return sqrt_ap(fdivf_(GAMMA_F * p, rho + 2.5f * p));
}

// vstar in log space: tanh(atanh_v + coeff*(lg2(SG-cs)-lg2(SG+cs)+lgK))
__device__ __forceinline__ float vstar_log(float cs, float atanh_v, float lgK, float coeff){
    float t = __log2f(SG_F - cs) - __log2f(SG_F + cs) + lgK;
    return tanh_ap(fmaf(coeff, t, atanh_v));
}

// bisection rarefaction solver; sgn = +1 (left) / -1 (right)
__device__ __forceinline__ void raref_solve(
    float rho_a, float p_a, float sgn, float atanh_v, float lgK,
    float& rho_o, float& p_o, float& h_o, float& v_o)
{
    float coeff = sgn * LN2_SG;
    float lo = 1e-6f;
    float hi = SG_F - 1e-6f;
    float flo = vstar_log(lo, atanh_v, lgK, coeff) - sgn * lo;
    #pragma unroll 1
    for (int i = 0; i < 20; i++){
        float mid = 0.5f * (lo + hi);
        float fm = vstar_log(mid, atanh_v, lgK, coeff) - sgn * mid;
        bool same = ((fm > 0.0f) == (flo > 0.0f)) && ((fm < 0.0f) == (flo > 0.0f ? -1.0f : 1.0f) == false);
        // (rewritten below for clarity; keep simple sign test)
        same = ((fm > 0.0f) == (flo > 0.0f));
        if (same){ lo = mid; flo = fm; } else { hi = mid; }
    }
    float cs = 0.5f * (lo + hi);
    float h  = fdivf_(GM1_F, GM1_F - cs * cs);
    float k  = (h - 1.0f) * 0.4f;
    float base = fdivf_(k * __powf(rho_a, GAMMA_F), p_a);
    rho_o = base * sqrt_ap(base);
    p_o   = k * rho_o;
    h_o   = h;
    v_o   = sgn * cs;
}

// shared-memory layout (floats)
#define OFF_W1T 0        // [5][6][32]  = 960 (transposed: e,f,h)
#define OFF_W2  960      // [5][32][32] = 5120 (e,g,h)
#define OFF_B1  6080     // [5][32]
#define OFF_B2  6240     // [5][32]
#define OFF_W3  6400     // [5][32]
#define OFF_B3  6560     // [5] (+pad)
#define SM_TOT  6568

// per-cell physics phase: argmin over ensemble + wave speeds + flux selection
__device__ __forceinline__ void physics_phase(
    int n, int NC, const float* __restrict__ P, const float* __restrict__ F,
    const float* __restrict__ pc, float* __restrict__ out)
{
    int cc = n < NC ? n : NC - 1;
    const float* Pb = P + (size_t)cc * 6;
    float rhoL = Pb[0], rhoR = Pb[1];
    float pL   = Pb[2], pR   = Pb[3];
    float vL   = Pb[4], vR   = Pb[5];

    float csL = csnd(rhoL, pL);
    float csR = csnd(rhoR, pR);
    float atanhL = HLN2 * (__log2f(1.0f + vL) - __log2f(1.0f - vL));
    float atanhR = HLN2 * (__log2f(1.0f + vR) - __log2f(1.0f - vR));
    float lgKL = __log2f(SG_F + csL) - __log2f(SG_F - csL);
    float lgKR = __log2f(SG_F + csR) - __log2f(SG_F - csR);
    float invpL = fdivf_(1.0f, pL);
    float invpR = fdivf_(1.0f, pR);

    float bestd = 1e30f;
    float s_press = 0.f, s_rhoCL = 0.f, s_hCL = 0.f, s_csCL = 0.f, s_vstarL = 0.f;
    float s_rhoCR = 0.f, s_hCR = 0.f, s_csCR = 0.f, s_vstarR = 0.f;

    #pragma unroll
    for (int e = 0; e < 5; e++){
        float p_c = pc[e];
        float rhoCL = rhoL * __powf(p_c * invpL, 0.6f);
        float hCL   = 1.0f + 2.5f * fdivf_(p_c, rhoCL);
        float csCL  = sqrt_ap(fdivf_(GAMMA_F * p_c, rhoCL + 2.5f * p_c));
        float vsL   = vstar_log(csCL, atanhL, lgKL, +LN2_SG);

        float rhoCR = rhoR * __powf(p_c * invpR, 0.6f);
        float hCR   = 1.0f + 2.5f * fdivf_(p_c, rhoCR);
        float csCR  = sqrt_ap(fdivf_(GAMMA_F * p_c, rhoCR + 2.5f * p_c));
        float vsR   = vstar_log(csCR, atanhR, lgKR, -LN2_SG);

        float d = fabsf(vsL - vsR);
        if (d < bestd){
            bestd = d; s_press = p_c;
            s_rhoCL = rhoCL; s_hCL = hCL; s_csCL = csCL; s_vstarL = vsL;
            s_rhoCR = rhoCR; s_hCR = hCR; s_csCR = csCR; s_vstarR = vsR;
        }
    }

    float lamC  = 0.5f * (s_vstarR + s_vstarL);
    float lamRL = fdivf_(lamC - s_csCL, 1.0f - lamC * s_csCL);
    float lamL  = fdivf_(vL - csL,     1.0f - vL * csL);
    float lamRR = fdivf_(lamC + s_csCR, 1.0f + lamC * s_csCR);
    float lamR  = fdivf_(vR + csR,     1.0f + vR * csR);

    int win = 0;
    if (lamL >= 0.0f)                   win = 1;
    if (lamL < 0.0f && lamRL >= 0.0f)   win = 2;
    if (lamRL < 0.0f && lamC > 0.0f)    win = 3;
    if (lamC <= 0.0f && lamRR > 0.0f)   win = 4;
    if (lamRR <= 0.0f && lamR > 0.0f)   win = 5;
    if (lamR <= 0.0f)                   win = 6;

    float f0 = 0.f, f1 = 0.f, f2 = 0.f;

    const float* Fb = F + (size_t)cc * 6;
    if (win == 1){ f0 = Fb[0]; f1 = Fb[2]; f2 = Fb[4]; }
    if (win == 6){ f0 = Fb[1]; f1 = Fb[3]; f2 = Fb[5]; }

    if (win == 3 || win == 4){
        float WC = rsqrtf(1.0f - lamC * lamC);
        float rc = (win == 3) ? s_rhoCL : s_rhoCR;
        float hc = (win == 3) ? s_hCL   : s_hCR;
        float dens = WC * rc;
        float mom  = WC * WC * rc * hc * lamC;
        f0 = dens * lamC;
        f1 = dens * (WC * hc - 1.0f) * lamC;
        f2 = mom * lamC + s_press;
    }

    bool needL = (win == 2);
    unsigned m = __activemask();
    if (__any_sync(m, needL)){
        float r_, p_, h_, v_;
        raref_solve(rhoL, pL, +1.0f, atanhL, lgKL, r_, p_, h_, v_);
        if (needL){
            float W_ = rsqrtf(1.0f - v_ * v_);
            float dens = W_ * r_;
            float mom  = W_ * W_ * r_ * h_ * v_;
            f0 = dens * v_;
            f1 = dens * (W_ * h_ - 1.0f) * v_;
            f2 = mom * v_ + p_;
        }
    }
    bool needR = (win == 5);
    if (__any_sync(m, needR)){
        float r_, p_, h_, v_;
        raref_solve(rhoR, pR, -1.0f, atanhR, lgKR, r_, p_, h_, v_);
        if (needR){
            float W_ = rsqrtf(1.0f - v_ * v_);
            float dens = W_ * r_;
            float mom  = W_ * W_ * r_ * h_ * v_;
            f0 = dens * v_;
            f1 = dens * (W_ * h_ - 1.0f) * v_;
            f2 = mom * v_ + p_;
        }
    }

    if (n < NC){
        float* ob = out + (size_t)n * 3;
        ob[0] = f0; ob[1] = f1; ob[2] = f2;
    }
}

__global__ void __launch_bounds__(NT)
ensemble_raref_kernel(
    const float* __restrict__ P,  const float* __restrict__ F,
    const float* __restrict__ W1, const float* __restrict__ b1,
    const float* __restrict__ W2, const float* __restrict__ b2,
    const float* __restrict__ W3, const float* __restrict__ b3,
    float* __restrict__ out, int NC)
{
    __shared__ __align__(16) float sm[SM_TOT];
    const int tid = threadIdx.x;

    for (int i = tid; i < 960; i += NT){
        int e = i / 192, r = i % 192, h = r / 6, f = r % 6;
        sm[OFF_W1T + e * 192 + f * 32 + h] = W1[i];
    }
    for (int i = tid; i < 5120; i += NT) sm[OFF_W2 + i] = W2[i];
    for (int i = tid; i < 160; i += NT){
        sm[OFF_B1 + i] = b1[i];
        sm[OFF_B2 + i] = b2[i];
        sm[OFF_W3 + i] = W3[i];
    }
    if (tid < 5) sm[OFF_B3 + tid] = b3[tid];
    __syncthreads();

    const int base = blockIdx.x * (2 * NT);
    const int na = base + tid;
    const int nb = base + NT + tid;
    const int ca = na < NC ? na : NC - 1;
    const int cb = nb < NC ? nb : NC - 1;

    // ---- Phase A: MLP for both cells (weight LDS shared) ----
    float pca[5], pcb[5];
    float pmin_a, pmin_b;
    float xa[6], xb[6];
    {
        const float* Pa = P + (size_t)ca * 6;
        const float* Pb = P + (size_t)cb * 6;
        float a0 = Pa[0], a1 = Pa[1], a2 = Pa[2], a3 = Pa[3], a4 = Pa[4], a5 = Pa[5];
        float b0 = Pb[0], b1_ = Pb[1], b2_ = Pb[2], b3_ = Pb[3], b4 = Pb[4], b5 = Pb[5];
        xa[0] = __logf(a0); xa[1] = __logf(a1); xa[2] = __logf(a2); xa[3] = __logf(a3);
        xa[4] = a4; xa[5] = a5;
        xb[0] = __logf(b0); xb[1] = __logf(b1_); xb[2] = __logf(b2_); xb[3] = __logf(b3_);
        xb[4] = b4; xb[5] = b5;
        pmin_a = fminf(a2, a3);
        pmin_b = fminf(b2_, b3_);
    }

    #pragma unroll 1
    for (int e = 0; e < 5; e++){
        const float* w1  = &sm[OFF_W1T + e * 192];

        u64 ha[16], hb[16];
        {
            const ulonglong2* bp = (const ulonglong2*)&sm[OFF_B1 + e * 32];
            #pragma unroll
            for (int q = 0; q < 8; q++){
                ulonglong2 b = bp[q];
                ha[2*q] = b.x; ha[2*q+1] = b.y;
                hb[2*q] = b.x; hb[2*q+1] = b.y;
            }
        }
        #pragma unroll
        for (int f = 0; f < 6; f++){
            u64 xpa = pk2(xa[f], xa[f]);
            u64 xpb = pk2(xb[f], xb[f]);
            const ulonglong2* wrow = (const ulonglong2*)(w1 + f * 32);
            #pragma unroll
            for (int q = 0; q < 8; q++){
                ulonglong2 w = wrow[q];
                ha[2*q]   = fma2(xpa, w.x, ha[2*q]);
                ha[2*q+1] = fma2(xpa, w.y, ha[2*q+1]);
                hb[2*q]   = fma2(xpb, w.x, hb[2*q]);
                hb[2*q+1] = fma2(xpb, w.y, hb[2*q+1]);
            }
        }
        #pragma unroll
        for (int q = 0; q < 16; q++){
            float u, v;
            upk2(ha[q], u, v); ha[q] = pk2(tanh_ap(u), tanh_ap(v));
            upk2(hb[q], u, v); hb[q] = pk2(tanh_ap(u), tanh_ap(v));
        }

        const float* w2  = &sm[OFF_W2 + e * 1024];
        const float* bb2 = &sm[OFF_B2 + e * 32];
        const float* w3  = &sm[OFF_W3 + e * 32];
        float logit_a = sm[OFF_B3 + e];
        float logit_b = logit_a;
        #pragma unroll 4
        for (int g = 0; g < 32; g++){
            float bg = bb2[g];
            u64 acc_a0 = pk2(bg, 0.0f), acc_a1 = pk2(0.0f, 0.0f);
            u64 acc_b0 = pk2(bg, 0.0f), acc_b1 = pk2(0.0f, 0.0f);
            const ulonglong2* wrow = (const ulonglong2*)(w2 + g * 32);
            #pragma unroll
            for (int q = 0; q < 8; q++){
                ulonglong2 w = wrow[q];
                acc_a0 = fma2(ha[2*q],   w.x, acc_a0);
                acc_a1 = fma2(ha[2*q+1], w.y, acc_a1);
                acc_b0 = fma2(hb[2*q],   w.x, acc_b0);
                acc_b1 = fma2(hb[2*q+1], w.y, acc_b1);
            }
            float wg = w3[g];
            u64 sa = add2(acc_a0, acc_a1);
            u64 sb = add2(acc_b0, acc_b1);
            float s0, s1;
            upk2(sa, s0, s1); logit_a = fmaf(wg, tanh_ap(s0 + s1), logit_a);
            upk2(sb, s0, s1); logit_b = fmaf(wg, tanh_ap(s0 + s1), logit_b);
        }
        pca[e] = fmaf(0.5f, tanh_ap(0.5f * logit_a), 0.5f) * pmin_a;
        pcb[e] = fmaf(0.5f, tanh_ap(0.5f * logit_b), 0.5f) * pmin_b;
    }

    // ---- Phase B: physics per cell ----
    physics_phase(na, NC, P, F, pca, out);
    physics_phase(nb, NC, P, F, pcb, out);
}

extern "C" void kernel_launch(void* const* d_in, const int* in_sizes, int n_in,
                              void* d_out, int out_size)
{
    const float* P  = (const float*)d_in[0];
    const float* F  = (const float*)d_in[2];
    const float* W1 = (const float*)d_in[5];
    const float* b1 = (const float*)d_in[6];
    const float* W2 = (const float*)d_in[7];
    const float* b2 = (const float*)d_in[8];
    const float* W3 = (const float*)d_in[9];
    const float* b3 = (const float*)d_in[10];
    float* out = (float*)d_out;

    int NC = in_sizes[0] / 6;
    int cellsPerBlock = 2 * NT;
    int grid = (NC + cellsPerBlock - 1) / cellsPerBlock;
    ensemble_raref_kernel<<<grid, NT>>>(P, F, W1, b1, W2, b2, W3, b3, out, NC);
}

// round 6
// speedup vs baseline: 2.4729x; 1.8839x over previous
#include <cuda_runtime.h>
#include <cuda_bf16.h>

#define NT 128

typedef unsigned int uint;

// physics constants (gamma = 5/3)
#define GAMMA_F   1.6666666666666667f
#define SG_F      0.8164965809277260f   // sqrt(gamma-1)
#define GM1_F     0.6666666666666667f   // gamma-1
#define LN2_SG    0.8489271574f         // ln2 / SG
#define HLN2      0.3465735903f         // 0.5*ln2

__device__ __forceinline__ float fdivf_(float a, float b){ return __fdividef(a, b); }

__device__ __forceinline__ float tanh_ap(float x){
    float y; asm("tanh.approx.f32 %0, %1;" : "=f"(y) : "f"(x)); return y;
}
__device__ __forceinline__ float sqrt_ap(float x){
    float y; asm("sqrt.approx.f32 %0, %1;" : "=f"(y) : "f"(x)); return y;
}

// pack two f32 -> bf16x2 (lo -> lower 16 bits, hi -> upper 16 bits)
__device__ __forceinline__ uint pack_bf16x2(float lo, float hi){
    uint r; asm("cvt.rn.satfinite.bf16x2.f32 %0, %1, %2;" : "=r"(r) : "f"(hi), "f"(lo)); return r;
}
// reconstruct the two f32 values a packed bf16x2 represents
__device__ __forceinline__ void bf16x2_vals(uint p, float& lo, float& hi){
    lo = __uint_as_float(p << 16);
    hi = __uint_as_float(p & 0xffff0000u);
}

__device__ __forceinline__ void mma_k8(float* c, uint a0, uint a1, uint b0){
    asm volatile("mma.sync.aligned.m16n8k8.row.col.f32.bf16.bf16.f32 "
        "{%0,%1,%2,%3},{%4,%5},{%6},{%0,%1,%2,%3};"
        : "+f"(c[0]), "+f"(c[1]), "+f"(c[2]), "+f"(c[3])
        : "r"(a0), "r"(a1), "r"(b0));
}
__device__ __forceinline__ void mma_k16(float* c, const uint* a, uint b0, uint b1){
    asm volatile("mma.sync.aligned.m16n8k16.row.col.f32.bf16.bf16.f32 "
        "{%0,%1,%2,%3},{%4,%5,%6,%7},{%8,%9},{%0,%1,%2,%3};"
        : "+f"(c[0]), "+f"(c[1]), "+f"(c[2]), "+f"(c[3])
        : "r"(a[0]), "r"(a[1]), "r"(a[2]), "r"(a[3]), "r"(b0), "r"(b1));
}

__device__ __forceinline__ float csnd(float rho, float p){
    return sqrt_ap(fdivf_(GAMMA_F * p, rho + 2.5f * p));
}

__device__ __forceinline__ float vstar_log(float cs, float atanh_v, float lgK, float coeff){
    float t = __log2f(SG_F - cs) - __log2f(SG_F + cs) + lgK;
    return tanh_ap(fmaf(coeff, t, atanh_v));
}

__device__ __forceinline__ void raref_solve(
    float rho_a, float p_a, float sgn, float atanh_v, float lgK,
    float& rho_o, float& p_o, float& h_o, float& v_o)
{
    float coeff = sgn * LN2_SG;
    float lo = 1e-6f;
    float hi = SG_F - 1e-6f;
    float flo = vstar_log(lo, atanh_v, lgK, coeff) - sgn * lo;
    #pragma unroll 1
    for (int i = 0; i < 20; i++){
        float mid = 0.5f * (lo + hi);
        float fm = vstar_log(mid, atanh_v, lgK, coeff) - sgn * mid;
        bool same = ((fm > 0.0f) == (flo > 0.0f));
        if (same){ lo = mid; flo = fm; } else { hi = mid; }
    }
    float cs = 0.5f * (lo + hi);
    float h  = fdivf_(GM1_F, GM1_F - cs * cs);
    float k  = (h - 1.0f) * 0.4f;
    float base = fdivf_(k * __powf(rho_a, GAMMA_F), p_a);
    rho_o = base * sqrt_ap(base);
    p_o   = k * rho_o;
    h_o   = h;
    v_o   = sgn * cs;
}

// per-cell physics: argmin over ensemble + wave speeds + flux selection
__device__ __forceinline__ void physics_phase(
    int n, int NC, const float* __restrict__ P, const float* __restrict__ F,
    const float* __restrict__ pc, float* __restrict__ out)
{
    int cc = n < NC ? n : NC - 1;
    const float* Pb = P + (size_t)cc * 6;
    float rhoL = Pb[0], rhoR = Pb[1];
    float pL   = Pb[2], pR   = Pb[3];
    float vL   = Pb[4], vR   = Pb[5];

    float csL = csnd(rhoL, pL);
    float csR = csnd(rhoR, pR);
    float atanhL = HLN2 * (__log2f(1.0f + vL) - __log2f(1.0f - vL));
    float atanhR = HLN2 * (__log2f(1.0f + vR) - __log2f(1.0f - vR));
    float lgKL = __log2f(SG_F + csL) - __log2f(SG_F - csL);
    float lgKR = __log2f(SG_F + csR) - __log2f(SG_F - csR);
    float invpL = fdivf_(1.0f, pL);
    float invpR = fdivf_(1.0f, pR);

    float bestd = 1e30f;
    float s_press = 0.f, s_rhoCL = 0.f, s_hCL = 0.f, s_csCL = 0.f, s_vstarL = 0.f;
    float s_rhoCR = 0.f, s_hCR = 0.f, s_csCR = 0.f, s_vstarR = 0.f;

    #pragma unroll
    for (int e = 0; e < 5; e++){
        float p_c = pc[e];
        float rhoCL = rhoL * __powf(p_c * invpL, 0.6f);
        float hCL   = 1.0f + 2.5f * fdivf_(p_c, rhoCL);
        float csCL  = sqrt_ap(fdivf_(GAMMA_F * p_c, rhoCL + 2.5f * p_c));
        float vsL   = vstar_log(csCL, atanhL, lgKL, +LN2_SG);

        float rhoCR = rhoR * __powf(p_c * invpR, 0.6f);
        float hCR   = 1.0f + 2.5f * fdivf_(p_c, rhoCR);
        float csCR  = sqrt_ap(fdivf_(GAMMA_F * p_c, rhoCR + 2.5f * p_c));
        float vsR   = vstar_log(csCR, atanhR, lgKR, -LN2_SG);

        float d = fabsf(vsL - vsR);
        if (d < bestd){
            bestd = d; s_press = p_c;
            s_rhoCL = rhoCL; s_hCL = hCL; s_csCL = csCL; s_vstarL = vsL;
            s_rhoCR = rhoCR; s_hCR = hCR; s_csCR = csCR; s_vstarR = vsR;
        }
    }

    float lamC  = 0.5f * (s_vstarR + s_vstarL);
    float lamRL = fdivf_(lamC - s_csCL, 1.0f - lamC * s_csCL);
    float lamL  = fdivf_(vL - csL,     1.0f - vL * csL);
    float lamRR = fdivf_(lamC + s_csCR, 1.0f + lamC * s_csCR);
    float lamR  = fdivf_(vR + csR,     1.0f + vR * csR);

    int win = 0;
    if (lamL >= 0.0f)                   win = 1;
    if (lamL < 0.0f && lamRL >= 0.0f)   win = 2;
    if (lamRL < 0.0f && lamC > 0.0f)    win = 3;
    if (lamC <= 0.0f && lamRR > 0.0f)   win = 4;
    if (lamRR <= 0.0f && lamR > 0.0f)   win = 5;
    if (lamR <= 0.0f)                   win = 6;

    float f0 = 0.f, f1 = 0.f, f2 = 0.f;

    const float* Fb = F + (size_t)cc * 6;
    if (win == 1){ f0 = Fb[0]; f1 = Fb[2]; f2 = Fb[4]; }
    if (win == 6){ f0 = Fb[1]; f1 = Fb[3]; f2 = Fb[5]; }

    if (win == 3 || win == 4){
        float WC = rsqrtf(1.0f - lamC * lamC);
        float rc = (win == 3) ? s_rhoCL : s_rhoCR;
        float hc = (win == 3) ? s_hCL   : s_hCR;
        float dens = WC * rc;
        float mom  = WC * WC * rc * hc * lamC;
        f0 = dens * lamC;
        f1 = dens * (WC * hc - 1.0f) * lamC;
        f2 = mom * lamC + s_press;
    }

    bool needL = (win == 2);
    unsigned m = __activemask();
    if (__any_sync(m, needL)){
        float r_, p_, h_, v_;
        raref_solve(rhoL, pL, +1.0f, atanhL, lgKL, r_, p_, h_, v_);
        if (needL){
            float W_ = rsqrtf(1.0f - v_ * v_);
            float dens = W_ * r_;
            float mom  = W_ * W_ * r_ * h_ * v_;
            f0 = dens * v_;
            f1 = dens * (W_ * h_ - 1.0f) * v_;
            f2 = mom * v_ + p_;
        }
    }
    bool needR = (win == 5);
    if (__any_sync(m, needR)){
        float r_, p_, h_, v_;
        raref_solve(rhoR, pR, -1.0f, atanhR, lgKR, r_, p_, h_, v_);
        if (needR){
            float W_ = rsqrtf(1.0f - v_ * v_);
            float dens = W_ * r_;
            float mom  = W_ * W_ * r_ * h_ * v_;
            f0 = dens * v_;
            f1 = dens * (W_ * h_ - 1.0f) * v_;
            f2 = mom * v_ + p_;
        }
    }

    if (n < NC){
        float* ob = out + (size_t)n * 3;
        ob[0] = f0; ob[1] = f1; ob[2] = f2;
    }
}

__global__ void __launch_bounds__(NT)
ensemble_raref_kernel(
    const float* __restrict__ P,  const float* __restrict__ F,
    const float* __restrict__ W1, const float* __restrict__ b1,
    const float* __restrict__ W2, const float* __restrict__ b2,
    const float* __restrict__ W3, const float* __restrict__ b3,
    float* __restrict__ out, int NC)
{
    // weights pre-split to bf16 hi/lo
    __shared__ __align__(16) __nv_bfloat16 sW1h[5*32*8], sW1l[5*32*8];   // [e][h][f(pad8)]
    __shared__ __align__(16) __nv_bfloat16 sW2h[5*32*32], sW2l[5*32*32]; // [e][g][h]
    __shared__ __align__(16) float sB1[5*32];
    __shared__ __align__(16) float sB2[5*32];
    __shared__ __align__(16) float sW3[5*32];
    __shared__ __align__(16) float sB3[8];
    __shared__ __align__(16) float sXI[4][32][5];   // per-warp xi redistribution

    const int tid = threadIdx.x;

    // ---- weight prep ----
    for (int i = tid; i < 160; i += NT){   // i = e*32 + h
        int e = i >> 5, h = i & 31;
        #pragma unroll
        for (int f = 0; f < 8; f++){
            float w = (f < 6) ? W1[e*192 + h*6 + f] : 0.0f;
            __nv_bfloat16 wh = __float2bfloat16_rn(w);
            __nv_bfloat16 wl = __float2bfloat16_rn(w - __bfloat162float(wh));
            sW1h[i*8 + f] = wh;
            sW1l[i*8 + f] = wl;
        }
        sB1[i] = b1[i]; sB2[i] = b2[i]; sW3[i] = W3[i];
    }
    for (int i = tid; i < 5120; i += NT){
        float w = W2[i];
        __nv_bfloat16 wh = __float2bfloat16_rn(w);
        sW2h[i] = wh;
        sW2l[i] = __float2bfloat16_rn(w - __bfloat162float(wh));
    }
    if (tid < 5) sB3[tid] = b3[tid];
    __syncthreads();

    const int warp = tid >> 5;
    const int lane = tid & 31;
    const int G = lane >> 2;     // group id (row within tile)
    const int t = lane & 3;      // thread in group (col pair selector)

    const int cellbase = blockIdx.x * 128 + warp * 32;
    const int n = cellbase + lane;
    const int cc = n < NC ? n : NC - 1;

    // own cell inputs
    float pmin;
    uint xph[3], xpl[3];
    {
        const float* Pb = P + (size_t)cc * 6;
        float x0 = __logf(Pb[0]), x1 = __logf(Pb[1]);
        float x2 = __logf(Pb[2]), x3 = __logf(Pb[3]);
        float x4 = Pb[4], x5 = Pb[5];
        pmin = fminf(Pb[2], Pb[3]);
        float xs[6] = {x0, x1, x2, x3, x4, x5};
        #pragma unroll
        for (int p = 0; p < 3; p++){
            uint hp = pack_bf16x2(xs[2*p], xs[2*p+1]);
            float hl, hh; bf16x2_vals(hp, hl, hh);
            xph[p] = hp;
            xpl[p] = pack_bf16x2(xs[2*p] - hl, xs[2*p+1] - hh);
        }
    }

    // layer-1 A fragments (m16k8) for 2 M-tiles, via shuffle gather
    uint a1h[2][2], a1l[2][2];
    #pragma unroll
    for (int i = 0; i < 2; i++){
        #pragma unroll
        for (int s = 0; s < 2; s++){
            int src = 16*i + G + 8*s;
            uint v0 = __shfl_sync(0xffffffffu, xph[0], src);
            uint v1 = __shfl_sync(0xffffffffu, xph[1], src);
            uint v2 = __shfl_sync(0xffffffffu, xph[2], src);
            a1h[i][s] = (t == 0) ? v0 : (t == 1) ? v1 : (t == 2) ? v2 : 0u;
            uint w0 = __shfl_sync(0xffffffffu, xpl[0], src);
            uint w1_ = __shfl_sync(0xffffffffu, xpl[1], src);
            uint w2_ = __shfl_sync(0xffffffffu, xpl[2], src);
            a1l[i][s] = (t == 0) ? w0 : (t == 1) ? w1_ : (t == 2) ? w2_ : 0u;
        }
    }

    // ---- ensemble loop ----
    #pragma unroll 1
    for (int e = 0; e < 5; e++){
        // layer 1: D1 = X * W1^T + b1   (2 Mtiles x 4 Ntiles)
        float c1[2][4][4];
        const uint* w1h = (const uint*)sW1h;
        const uint* w1l = (const uint*)sW1l;
        #pragma unroll
        for (int j = 0; j < 4; j++){
            float2 bb = *(const float2*)&sB1[e*32 + 8*j + 2*t];
            uint bh = w1h[(e*32 + 8*j + G)*4 + t];
            uint bl = w1l[(e*32 + 8*j + G)*4 + t];
            #pragma unroll
            for (int i = 0; i < 2; i++){
                float* cfr = c1[i][j];
                cfr[0] = bb.x; cfr[1] = bb.y; cfr[2] = bb.x; cfr[3] = bb.y;
                mma_k8(cfr, a1h[i][0], a1h[i][1], bh);
                mma_k8(cfr, a1l[i][0], a1l[i][1], bh);
                mma_k8(cfr, a1h[i][0], a1h[i][1], bl);
            }
        }

        // tanh + bf16 split -> layer-2 A fragments (m16k16, 2 k-tiles)
        uint A2h[2][2][4], A2l[2][2][4];
        #pragma unroll
        for (int i = 0; i < 2; i++){
            #pragma unroll
            for (int jk = 0; jk < 2; jk++){
                float v[8];
                v[0] = tanh_ap(c1[i][2*jk][0]);   v[1] = tanh_ap(c1[i][2*jk][1]);
                v[2] = tanh_ap(c1[i][2*jk][2]);   v[3] = tanh_ap(c1[i][2*jk][3]);
                v[4] = tanh_ap(c1[i][2*jk+1][0]); v[5] = tanh_ap(c1[i][2*jk+1][1]);
                v[6] = tanh_ap(c1[i][2*jk+1][2]); v[7] = tanh_ap(c1[i][2*jk+1][3]);
                // a0 <- (v0,v1) ; a1 <- (v2,v3) ; a2 <- (v4,v5) ; a3 <- (v6,v7)
                #pragma unroll
                for (int q = 0; q < 4; q++){
                    uint hp = pack_bf16x2(v[2*q], v[2*q+1]);
                    float hl, hh; bf16x2_vals(hp, hl, hh);
                    A2h[i][jk][q] = hp;
                    A2l[i][jk][q] = pack_bf16x2(v[2*q] - hl, v[2*q+1] - hh);
                }
            }
        }

        // layer 2: D2 = tanh(D1) * W2^T + b2
        float d2[2][4][4];
        const uint* w2h = (const uint*)sW2h;
        const uint* w2l = (const uint*)sW2l;
        #pragma unroll
        for (int jn = 0; jn < 4; jn++){
            float2 bb = *(const float2*)&sB2[e*32 + 8*jn + 2*t];
            #pragma unroll
            for (int i = 0; i < 2; i++){
                float* dfr = d2[i][jn];
                dfr[0] = bb.x; dfr[1] = bb.y; dfr[2] = bb.x; dfr[3] = bb.y;
            }
            #pragma unroll
            for (int jk = 0; jk < 2; jk++){
                int rb = e*1024 + (8*jn + G)*32 + 16*jk + 2*t;  // bf16 index, even
                uint b0h = w2h[rb >> 1];
                uint b1h = w2h[(rb + 8) >> 1];
                uint b0l = w2l[rb >> 1];
                uint b1l = w2l[(rb + 8) >> 1];
                #pragma unroll
                for (int i = 0; i < 2; i++){
                    mma_k16(d2[i][jn], A2h[i][jk], b0h, b1h);
                    mma_k16(d2[i][jn], A2l[i][jk], b0h, b1h);
                    mma_k16(d2[i][jn], A2h[i][jk], b0l, b1l);
                }
            }
        }

        // layer 3: logit = b3 + sum_g w3[g] * tanh(d2[g])
        float lg0[2] = {0.f, 0.f};   // row G    per mtile
        float lg1[2] = {0.f, 0.f};   // row G+8  per mtile
        #pragma unroll
        for (int jn = 0; jn < 4; jn++){
            float2 w3p = *(const float2*)&sW3[e*32 + 8*jn + 2*t];
            #pragma unroll
            for (int i = 0; i < 2; i++){
                lg0[i] = fmaf(w3p.x, tanh_ap(d2[i][jn][0]), lg0[i]);
                lg0[i] = fmaf(w3p.y, tanh_ap(d2[i][jn][1]), lg0[i]);
                lg1[i] = fmaf(w3p.x, tanh_ap(d2[i][jn][2]), lg1[i]);
                lg1[i] = fmaf(w3p.y, tanh_ap(d2[i][jn][3]), lg1[i]);
            }
        }
        #pragma unroll
        for (int i = 0; i < 2; i++){
            lg0[i] += __shfl_xor_sync(0xffffffffu, lg0[i], 1);
            lg0[i] += __shfl_xor_sync(0xffffffffu, lg0[i], 2);
            lg1[i] += __shfl_xor_sync(0xffffffffu, lg1[i], 1);
            lg1[i] += __shfl_xor_sync(0xffffffffu, lg1[i], 2);
        }
        float b3v = sB3[e];
        if (t == 0){
            #pragma unroll
            for (int i = 0; i < 2; i++){
                sXI[warp][16*i + G][e]     = fmaf(0.5f, tanh_ap(0.5f * (lg0[i] + b3v)), 0.5f);
                sXI[warp][16*i + G + 8][e] = fmaf(0.5f, tanh_ap(0.5f * (lg1[i] + b3v)), 0.5f);
            }
        }
    }

    __syncwarp();

    float pc[5];
    #pragma unroll
    for (int k = 0; k < 5; k++) pc[k] = sXI[warp][lane][k] * pmin;

    physics_phase(n, NC, P, F, pc, out);
}

extern "C" void kernel_launch(void* const* d_in, const int* in_sizes, int n_in,
                              void* d_out, int out_size)
{
    const float* P  = (const float*)d_in[0];
    const float* F  = (const float*)d_in[2];
    const float* W1 = (const float*)d_in[5];
    const float* b1 = (const float*)d_in[6];
    const float* W2 = (const float*)d_in[7];
    const float* b2 = (const float*)d_in[8];
    const float* W3 = (const float*)d_in[9];
    const float* b3 = (const float*)d_in[10];
    float* out = (float*)d_out;

    int NC = in_sizes[0] / 6;
    int grid = (NC + 127) / 128;
    ensemble_raref_kernel<<<grid, NT>>>(P, F, W1, b1, W2, b2, W3, b3, out, NC);
}